// round 15
// baseline (speedup 1.0000x reference)
#include <cuda_runtime.h>
#include <cuda_bf16.h>
#include <cstdint>

// Problem constants
#define BB 4
#define TT 2048
#define DD 1024
#define NHEAD 16
#define HD 64
#define NTOK (BB * TT)          // 8192

// ---------------------------------------------------------------------------
// Scratch (device globals; allocation is forbidden)
// ---------------------------------------------------------------------------
__device__ __nv_bfloat16 g_xhi[(size_t)NTOK * DD];
__device__ __nv_bfloat16 g_xlo[(size_t)NTOK * DD];
__device__ __nv_bfloat16 g_Mhi[(size_t)3 * DD * DD];
__device__ __nv_bfloat16 g_Mlo[(size_t)3 * DD * DD];
__device__ __nv_bfloat16 g_Whi[(size_t)DD * DD];
__device__ __nv_bfloat16 g_Wlo[(size_t)DD * DD];
__device__ __nv_bfloat16 g_qvh[(size_t)NTOK * 3 * DD];  // qkv hi (QK: hi only)
__device__ __nv_bfloat16 g_qvl[(size_t)NTOK * 3 * DD];  // qkv lo (V region only)
__device__ __nv_bfloat16 g_zhi[(size_t)NTOK * DD];
__device__ __nv_bfloat16 g_zlo[(size_t)NTOK * DD];

// ---------------------------------------------------------------------------
// Helpers
// ---------------------------------------------------------------------------
__device__ __forceinline__ uint32_t smem_u32(const void* p) {
    uint32_t a;
    asm("{ .reg .u64 t; cvta.to.shared.u64 t, %1; cvt.u32.u64 %0, t; }" : "=r"(a) : "l"(p));
    return a;
}
__device__ __forceinline__ uint32_t swz(uint32_t o) { return o ^ ((o >> 3) & 0x70); }

__device__ __forceinline__ void cp16(uint32_t s, const void* g) {
    asm volatile("cp.async.cg.shared.global [%0], [%1], 16;" :: "r"(s), "l"(g) : "memory");
}
__device__ __forceinline__ void cp_commit() {
    asm volatile("cp.async.commit_group;" ::: "memory");
}
__device__ __forceinline__ void ldsm4(uint32_t (&r)[4], uint32_t addr) {
    asm volatile("ldmatrix.sync.aligned.m8n8.x4.shared.b16 {%0,%1,%2,%3}, [%4];"
                 : "=r"(r[0]), "=r"(r[1]), "=r"(r[2]), "=r"(r[3]) : "r"(addr));
}
__device__ __forceinline__ void ldsm4t(uint32_t (&r)[4], uint32_t addr) {
    asm volatile("ldmatrix.sync.aligned.m8n8.x4.trans.shared.b16 {%0,%1,%2,%3}, [%4];"
                 : "=r"(r[0]), "=r"(r[1]), "=r"(r[2]), "=r"(r[3]) : "r"(addr));
}
__device__ __forceinline__ void mma16816(float (&d)[4], const uint32_t (&a)[4],
                                         uint32_t b0, uint32_t b1) {
    asm volatile("mma.sync.aligned.m16n8k16.row.col.f32.bf16.bf16.f32 "
                 "{%0,%1,%2,%3}, {%4,%5,%6,%7}, {%8,%9}, {%0,%1,%2,%3};"
                 : "+f"(d[0]), "+f"(d[1]), "+f"(d[2]), "+f"(d[3])
                 : "r"(a[0]), "r"(a[1]), "r"(a[2]), "r"(a[3]), "r"(b0), "r"(b1));
}
__device__ __forceinline__ uint32_t packbf(float lo, float hi) {
    uint32_t r;
    asm("cvt.rn.bf16x2.f32 %0, %1, %2;" : "=r"(r) : "f"(hi), "f"(lo));
    return r;
}
__device__ __forceinline__ float bfr(float f) {
    return __bfloat162float(__float2bfloat16(f));
}

// ---------------------------------------------------------------------------
// fp32 -> bf16 hi/lo split
// ---------------------------------------------------------------------------
__global__ __launch_bounds__(256) void split_bf16(const float* __restrict__ src,
                                                  __nv_bfloat16* __restrict__ hi,
                                                  __nv_bfloat16* __restrict__ lo,
                                                  int n4) {
    int i = blockIdx.x * blockDim.x + threadIdx.x;
    if (i >= n4) return;
    float4 v = ((const float4*)src)[i];
    float f[4] = {v.x, v.y, v.z, v.w};
    __nv_bfloat16 h[4], l[4];
#pragma unroll
    for (int j = 0; j < 4; j++) {
        h[j] = __float2bfloat16(f[j]);
        l[j] = __float2bfloat16(f[j] - __bfloat162float(h[j]));
    }
    ((uint2*)hi)[i] = *(uint2*)h;
    ((uint2*)lo)[i] = *(uint2*)l;
}

// ---------------------------------------------------------------------------
// QK projection GEMM (single-pass bf16): C = A[M,K]*B[N,K]^T, bf16 hi out.
//  CTA 128x128, 128 threads (4 warps, warp 64x64), NS=3 (96 KB) -> 2 CTAs/SM.
// ---------------------------------------------------------------------------
#define QK_ATILE 16384
#define QK_BTILE 16384
#define QK_STG   (QK_ATILE + QK_BTILE)   // 32768
#define QK_NS    3
#define QK_SMEM  (QK_NS * QK_STG)        // 98304

__global__ __launch_bounds__(128, 2)
void gemm_qk(const __nv_bfloat16* __restrict__ Ahi, const __nv_bfloat16* __restrict__ Bhi,
             __nv_bfloat16* __restrict__ Chi, int Ncols, int K) {
    extern __shared__ char smem[];
    const uint32_t sb = smem_u32(smem);
    const int tid = threadIdx.x;
    const int l   = tid & 31;
    const int wid = tid >> 5;
    const int row0 = blockIdx.y * 128;
    const int col0 = blockIdx.x * 128;
    const int wm0 = (wid & 1) * 64;
    const int wn0 = (wid >> 1) * 64;
    const int nchunk = K >> 6;

    const int lr_a = (l & 7) + ((l >> 3) & 1) * 8;
    const int ca   = ((l >> 4) & 1) * 8;
    const int lr_b = (l & 7) + ((l >> 4) & 1) * 8;
    const int cb   = ((l >> 3) & 1) * 8;

    float acc[4][8][4];
#pragma unroll
    for (int i = 0; i < 4; i++)
#pragma unroll
        for (int j = 0; j < 8; j++)
#pragma unroll
            for (int q = 0; q < 4; q++) acc[i][j][q] = 0.f;

    auto issue = [&](int buf, int k0) {
#pragma unroll
        for (int i = 0; i < 16; i++) {
            int u = tid + i * 128;           // 0..2047
            if (u < 1024) {
                int r = u >> 3, g = u & 7;
                cp16(sb + (uint32_t)buf * QK_STG + swz((uint32_t)(r * 128 + g * 16)),
                     Ahi + (size_t)(row0 + r) * K + k0 + g * 8);
            } else {
                int t = u - 1024;            // 0..1023
                int r = t >> 3, g = t & 7;   // r 0..127
                cp16(sb + (uint32_t)buf * QK_STG + QK_ATILE + swz((uint32_t)(r * 128 + g * 16)),
                     Bhi + (size_t)(col0 + r) * K + k0 + g * 8);
            }
        }
    };

#pragma unroll
    for (int s = 0; s < QK_NS - 1; s++) {
        issue(s, s << 6);
        cp_commit();
    }

    for (int c = 0; c < nchunk; c++) {
        asm volatile("cp.async.wait_group %0;" :: "n"(QK_NS - 2));
        __syncthreads();
        int cn = c + QK_NS - 1;
        if (cn < nchunk) issue(cn % QK_NS, cn << 6);
        cp_commit();

        const uint32_t stb = sb + (uint32_t)(c % QK_NS) * QK_STG;

#pragma unroll
        for (int ks = 0; ks < 4; ks++) {
            const int k0b = ks * 32;
            uint32_t ah[4][4];
#pragma unroll
            for (int i = 0; i < 4; i++)
                ldsm4(ah[i], stb + swz((uint32_t)((wm0 + i * 16 + lr_a) * 128 + k0b + ca * 2)));
            uint32_t bh[4][4];
#pragma unroll
            for (int jb = 0; jb < 4; jb++)
                ldsm4(bh[jb], stb + QK_ATILE + swz((uint32_t)((wn0 + jb * 16 + lr_b) * 128 + k0b + cb * 2)));
#pragma unroll
            for (int i = 0; i < 4; i++)
#pragma unroll
                for (int j = 0; j < 8; j++) {
                    int jb = j >> 1, p = (j & 1) * 2;
                    mma16816(acc[i][j], ah[i], bh[jb][p], bh[jb][p + 1]);
                }
        }
    }

    const int gq = l >> 2;
    const int tg = (l & 3) * 2;
#pragma unroll
    for (int i = 0; i < 4; i++) {
        int r = row0 + wm0 + i * 16 + gq;
#pragma unroll
        for (int j = 0; j < 8; j++) {
            int cc = col0 + wn0 + j * 8 + tg;
            size_t o0 = (size_t)r * Ncols + cc;
            size_t o1 = (size_t)(r + 8) * Ncols + cc;
            *reinterpret_cast<uint32_t*>(Chi + o0) = packbf(acc[i][j][0], acc[i][j][1]);
            *reinterpret_cast<uint32_t*>(Chi + o1) = packbf(acc[i][j][2], acc[i][j][3]);
        }
    }
}

// ---------------------------------------------------------------------------
// bf16x3 GEMM_NT (fp32-accurate):  C[M,N] = A[M,K] * B[N,K]^T
//  OMODE: 0 = fp32 C; 1 = bf16 hi/lo.
//  CTA 128x64, 128 threads (4 warps, warp 64x32), NS=2 (96 KB) -> 2 CTAs/SM.
// ---------------------------------------------------------------------------
#define GT_AT    16384                    // Ahi (128 rows x 128 B)
#define GT_BT    8192                     // Bhi (64 rows x 128 B)
#define GT_STG   (2 * GT_AT + 2 * GT_BT)  // 49152: {Ahi, Alo, Bhi, Blo}
#define GT_NS    2
#define GT_SMEM  (GT_NS * GT_STG)         // 98304

template <int OMODE>
__global__ __launch_bounds__(128, 2)
void gemm_t(const __nv_bfloat16* __restrict__ Ahi, const __nv_bfloat16* __restrict__ Alo,
            const __nv_bfloat16* __restrict__ Bhi, const __nv_bfloat16* __restrict__ Blo,
            float* __restrict__ C, __nv_bfloat16* __restrict__ Chi,
            __nv_bfloat16* __restrict__ Clo, int Ncols, int K) {
    extern __shared__ char smem[];
    const uint32_t sb = smem_u32(smem);
    const int tid = threadIdx.x;
    const int l   = tid & 31;
    const int wid = tid >> 5;
    const int row0 = blockIdx.y * 128;
    const int col0 = blockIdx.x * 64;
    const int wm0 = (wid & 1) * 64;
    const int wn0 = (wid >> 1) * 32;
    const int nchunk = K >> 6;

    const int lr_a = (l & 7) + ((l >> 3) & 1) * 8;
    const int ca   = ((l >> 4) & 1) * 8;
    const int lr_b = (l & 7) + ((l >> 4) & 1) * 8;
    const int cb   = ((l >> 3) & 1) * 8;

    float acc[4][4][4];
#pragma unroll
    for (int i = 0; i < 4; i++)
#pragma unroll
        for (int j = 0; j < 4; j++)
#pragma unroll
            for (int q = 0; q < 4; q++) acc[i][j][q] = 0.f;

    // stage layout: [Ahi 16K][Alo 16K][Bhi 8K][Blo 8K]
    auto issue = [&](int buf, int k0) {
        const uint32_t stg = sb + (uint32_t)buf * GT_STG;
#pragma unroll
        for (int i = 0; i < 24; i++) {
            int u = tid + i * 128;           // 0..3071
            if (u < 2048) {                  // A hi/lo: 2 x 1024
                int tl = u >> 10, t = u & 1023;
                int r = t >> 3, g = t & 7;
                const __nv_bfloat16* base = tl ? Alo : Ahi;
                cp16(stg + (uint32_t)tl * GT_AT + swz((uint32_t)(r * 128 + g * 16)),
                     base + (size_t)(row0 + r) * K + k0 + g * 8);
            } else {                         // B hi/lo: 2 x 512
                int t = u - 2048;
                int tl = t >> 9;  t &= 511;
                int r = t >> 3, g = t & 7;   // r 0..63
                const __nv_bfloat16* base = tl ? Blo : Bhi;
                cp16(stg + 2 * GT_AT + (uint32_t)tl * GT_BT + swz((uint32_t)(r * 128 + g * 16)),
                     base + (size_t)(col0 + r) * K + k0 + g * 8);
            }
        }
    };

    issue(0, 0);
    cp_commit();

    for (int c = 0; c < nchunk; c++) {
        asm volatile("cp.async.wait_group %0;" :: "n"(0));
        __syncthreads();
        if (c + 1 < nchunk) issue((c + 1) & 1, (c + 1) << 6);
        cp_commit();

        const uint32_t stb = sb + (uint32_t)(c & 1) * GT_STG;

#pragma unroll
        for (int ks = 0; ks < 4; ks++) {
            const int k0b = ks * 32;
            uint32_t ah[4][4], al[4][4];
#pragma unroll
            for (int i = 0; i < 4; i++) {
                uint32_t off = swz((uint32_t)((wm0 + i * 16 + lr_a) * 128 + k0b + ca * 2));
                ldsm4(ah[i], stb + off);
                ldsm4(al[i], stb + GT_AT + off);
            }
            uint32_t bh[2][4], bl[2][4];
#pragma unroll
            for (int h = 0; h < 2; h++) {
                uint32_t off = swz((uint32_t)((wn0 + h * 16 + lr_b) * 128 + k0b + cb * 2));
                ldsm4(bh[h], stb + 2 * GT_AT + off);
                ldsm4(bl[h], stb + 2 * GT_AT + GT_BT + off);
            }
            // pass 1: ah * bh
#pragma unroll
            for (int i = 0; i < 4; i++)
#pragma unroll
                for (int j = 0; j < 4; j++) {
                    int h = j >> 1, p = (j & 1) * 2;
                    mma16816(acc[i][j], ah[i], bh[h][p], bh[h][p + 1]);
                }
            // pass 2: ah * bl
#pragma unroll
            for (int i = 0; i < 4; i++)
#pragma unroll
                for (int j = 0; j < 4; j++) {
                    int h = j >> 1, p = (j & 1) * 2;
                    mma16816(acc[i][j], ah[i], bl[h][p], bl[h][p + 1]);
                }
            // pass 3: al * bh
#pragma unroll
            for (int i = 0; i < 4; i++)
#pragma unroll
                for (int j = 0; j < 4; j++) {
                    int h = j >> 1, p = (j & 1) * 2;
                    mma16816(acc[i][j], al[i], bh[h][p], bh[h][p + 1]);
                }
        }
    }

    const int gq = l >> 2;
    const int tg = (l & 3) * 2;
#pragma unroll
    for (int i = 0; i < 4; i++) {
        int r = row0 + wm0 + i * 16 + gq;
#pragma unroll
        for (int j = 0; j < 4; j++) {
            int cc = col0 + wn0 + j * 8 + tg;
            float v0 = acc[i][j][0], v1 = acc[i][j][1];
            float v2 = acc[i][j][2], v3 = acc[i][j][3];
            size_t o0 = (size_t)r * Ncols + cc;
            size_t o1 = (size_t)(r + 8) * Ncols + cc;
            if (OMODE == 0) {
                *(float2*)(C + o0) = make_float2(v0, v1);
                *(float2*)(C + o1) = make_float2(v2, v3);
            } else {
                float h0 = bfr(v0), h1 = bfr(v1), h2 = bfr(v2), h3 = bfr(v3);
                *reinterpret_cast<uint32_t*>(Chi + o0) = packbf(h0, h1);
                *reinterpret_cast<uint32_t*>(Clo + o0) = packbf(v0 - h0, v1 - h1);
                *reinterpret_cast<uint32_t*>(Chi + o1) = packbf(h2, h3);
                *reinterpret_cast<uint32_t*>(Clo + o1) = packbf(v2 - h2, v3 - h3);
            }
        }
    }
}

// ---------------------------------------------------------------------------
// Flash attention, mma.sync, no-max softmax (logits bounded -> shift 0 exact).
//  Br=64 (4 warps x m16), Bc=64, NS=2 stages (56 KB) -> 3 CTAs/SM.
//  Batch index passed as parameter (bbase) for per-batch pipelining.
// ---------------------------------------------------------------------------
#define ATT_TILE   8192
#define ATT_STAGE  (3 * ATT_TILE)                 // 24576: {Khi, Vhi, Vlo}
#define ATT_NS     2
#define ATT_SMEM   (ATT_TILE + ATT_NS * ATT_STAGE)   // 57344

__global__ __launch_bounds__(128, 3)
void attn_mma(const __nv_bfloat16* __restrict__ qvh, const __nv_bfloat16* __restrict__ qvl,
              __nv_bfloat16* __restrict__ zhi, __nv_bfloat16* __restrict__ zlo,
              int bbase) {
    extern __shared__ char smem[];
    const uint32_t sb = smem_u32(smem);
    const int tid = threadIdx.x, l = tid & 31, w = tid >> 5;
    const int qi = (TT / 64 - 1) - blockIdx.x;   // heavy CTAs first
    const int head = blockIdx.y, b = bbase;
    const int t0 = qi * 64;
    const int colK = head * HD;            // Qproj = keys
    const int colQ = DD + head * HD;       // Kproj = queries
    const int colV = 2 * DD + head * HD;   // V

    const int lr   = (l & 7) + ((l >> 3) & 1) * 8;
    const int ca16 = ((l >> 4) & 1) * 16;
    const int lr_b = (l & 7) + ((l >> 4) & 1) * 8;
    const int cb16 = ((l >> 3) & 1) * 16;

    auto issue_kv = [&](int kt, int buf) {
        const uint32_t stg = sb + ATT_TILE + (uint32_t)buf * ATT_STAGE;
#pragma unroll
        for (int i = 0; i < 12; i++) {
            int u = tid + i * 128;         // 0..1535
            int tl = u >> 9;               // 0:Khi 1:Vhi 2:Vlo
            int t = u & 511;
            int r = t >> 3, sg = t & 7;
            const __nv_bfloat16* base = (tl == 2) ? qvl : qvh;
            int col = tl ? colV : colK;
            cp16(stg + (uint32_t)tl * ATT_TILE + swz((uint32_t)(r * 128 + sg * 16)),
                 base + (size_t)(b * TT + kt * 64 + r) * (3 * DD) + col + sg * 8);
        }
    };

    // prologue: Q (hi only) + stage 0
#pragma unroll
    for (int i = 0; i < 4; i++) {
        int u = tid + i * 128;
        int r = u >> 3, sg = u & 7;
        cp16(sb + swz((uint32_t)(r * 128 + sg * 16)),
             qvh + (size_t)(b * TT + t0 + r) * (3 * DD) + colQ + sg * 8);
    }
    issue_kv(0, 0);
    cp_commit();

    float out[8][4];
#pragma unroll
    for (int j = 0; j < 8; j++)
#pragma unroll
        for (int q = 0; q < 4; q++) out[j][q] = 0.f;
    float ls0 = 0.f, ls1 = 0.f;   // lane-local; reduced in epilogue

    for (int kt = 0; kt <= qi; kt++) {
        asm volatile("cp.async.wait_group %0;" :: "n"(0));
        __syncthreads();
        if (kt + 1 <= qi) issue_kv(kt + 1, (kt + 1) & 1);
        cp_commit();

        const uint32_t stb = sb + ATT_TILE + (uint32_t)(kt & 1) * ATT_STAGE;

        // ---- S = Qhi . Khi^T (single pass) ----
        float sc[8][4];
#pragma unroll
        for (int j = 0; j < 8; j++)
#pragma unroll
            for (int q = 0; q < 4; q++) sc[j][q] = 0.f;
#pragma unroll
        for (int kk = 0; kk < 4; kk++) {
            uint32_t aqh[4];
            ldsm4(aqh, sb + swz((uint32_t)((w * 16 + lr) * 128 + kk * 32 + ca16)));
#pragma unroll
            for (int jb = 0; jb < 4; jb++) {
                uint32_t kbh[4];
                ldsm4(kbh, stb + swz((uint32_t)((jb * 16 + lr_b) * 128 + kk * 32 + cb16)));
                mma16816(sc[2 * jb],     aqh, kbh[0], kbh[1]);
                mma16816(sc[2 * jb + 1], aqh, kbh[2], kbh[3]);
            }
        }

        if (kt == qi) {   // diagonal tile: mask key i_local > t_local
            int tr0 = w * 16 + (l >> 2), tr1 = tr0 + 8;
            int ib = (l & 3) * 2;
#pragma unroll
            for (int j = 0; j < 8; j++) {
                int i0 = j * 8 + ib, i1 = i0 + 1;
                if (i0 > tr0) sc[j][0] = -1e30f;
                if (i1 > tr0) sc[j][1] = -1e30f;
                if (i0 > tr1) sc[j][2] = -1e30f;
                if (i1 > tr1) sc[j][3] = -1e30f;
            }
        }

        // ---- p = exp(s/8) (shift 0 exact; logits bounded) ----
#pragma unroll
        for (int j = 0; j < 8; j++) {
            sc[j][0] = __expf(sc[j][0] * 0.125f); ls0 += sc[j][0];
            sc[j][1] = __expf(sc[j][1] * 0.125f); ls0 += sc[j][1];
            sc[j][2] = __expf(sc[j][2] * 0.125f); ls1 += sc[j][2];
            sc[j][3] = __expf(sc[j][3] * 0.125f); ls1 += sc[j][3];
        }

        // ---- out += P.V  (pass-major: pah*vbh, pal*vbh, pah*vbl) ----
#pragma unroll
        for (int kk = 0; kk < 4; kk++) {
            uint32_t pah[4], pal[4];
#pragma unroll
            for (int h = 0; h < 2; h++) {
                int t2 = 2 * kk + h;
                float f0 = sc[t2][0], f1 = sc[t2][1], f2 = sc[t2][2], f3 = sc[t2][3];
                float h0 = bfr(f0), h1 = bfr(f1), h2 = bfr(f2), h3 = bfr(f3);
                pah[2 * h]     = packbf(h0, h1);
                pah[2 * h + 1] = packbf(h2, h3);
                pal[2 * h]     = packbf(f0 - h0, f1 - h1);
                pal[2 * h + 1] = packbf(f2 - h2, f3 - h3);
            }
            uint32_t vbh[4][4];
#pragma unroll
            for (int nb = 0; nb < 4; nb++)
                ldsm4t(vbh[nb], stb + ATT_TILE +
                       swz((uint32_t)((kk * 16 + lr) * 128 + nb * 32 + ca16)));
            // pass 1: pah * vbh
#pragma unroll
            for (int nb = 0; nb < 4; nb++) {
                mma16816(out[2 * nb],     pah, vbh[nb][0], vbh[nb][1]);
                mma16816(out[2 * nb + 1], pah, vbh[nb][2], vbh[nb][3]);
            }
            // pass 2: pal * vbh
#pragma unroll
            for (int nb = 0; nb < 4; nb++) {
                mma16816(out[2 * nb],     pal, vbh[nb][0], vbh[nb][1]);
                mma16816(out[2 * nb + 1], pal, vbh[nb][2], vbh[nb][3]);
            }
            // pass 3: pah * vbl
            uint32_t vbl[4][4];
#pragma unroll
            for (int nb = 0; nb < 4; nb++)
                ldsm4t(vbl[nb], stb + 2 * ATT_TILE +
                       swz((uint32_t)((kk * 16 + lr) * 128 + nb * 32 + ca16)));
#pragma unroll
            for (int nb = 0; nb < 4; nb++) {
                mma16816(out[2 * nb],     pah, vbl[nb][0], vbl[nb][1]);
                mma16816(out[2 * nb + 1], pah, vbl[nb][2], vbl[nb][3]);
            }
        }
    }

    // ---- epilogue: reduce lsum across quad, z = out / lsum, bf16 hi/lo ----
    ls0 += __shfl_xor_sync(0xffffffffu, ls0, 1);
    ls0 += __shfl_xor_sync(0xffffffffu, ls0, 2);
    ls1 += __shfl_xor_sync(0xffffffffu, ls1, 1);
    ls1 += __shfl_xor_sync(0xffffffffu, ls1, 2);
    float inv0 = 1.f / ls0, inv1 = 1.f / ls1;
    int tr0 = t0 + w * 16 + (l >> 2);
    size_t tok0 = (size_t)(b * TT + tr0) * DD;
    size_t tok1 = tok0 + (size_t)8 * DD;
    int colz = head * HD + (l & 3) * 2;
#pragma unroll
    for (int j = 0; j < 8; j++) {
        int cc = colz + j * 8;
        float v0 = out[j][0] * inv0, v1 = out[j][1] * inv0;
        float v2 = out[j][2] * inv1, v3 = out[j][3] * inv1;
        float h0 = bfr(v0), h1 = bfr(v1), h2 = bfr(v2), h3 = bfr(v3);
        *reinterpret_cast<uint32_t*>(zhi + tok0 + cc) = packbf(h0, h1);
        *reinterpret_cast<uint32_t*>(zlo + tok0 + cc) = packbf(v0 - h0, v1 - h1);
        *reinterpret_cast<uint32_t*>(zhi + tok1 + cc) = packbf(h2, h3);
        *reinterpret_cast<uint32_t*>(zlo + tok1 + cc) = packbf(v2 - h2, v3 - h3);
    }
}

// ---------------------------------------------------------------------------
extern "C" void kernel_launch(void* const* d_in, const int* in_sizes, int n_in,
                              void* d_out, int out_size) {
    const float* x = nullptr;
    const float* M = nullptr;
    const float* W = nullptr;
    for (int i = 0; i < n_in; i++) {
        if (in_sizes[i] == NTOK * DD)        x = (const float*)d_in[i];
        else if (in_sizes[i] == 3 * DD * DD) M = (const float*)d_in[i];
        else if (in_sizes[i] == DD * DD)     W = (const float*)d_in[i];
    }
    float* out = (float*)d_out;

    __nv_bfloat16 *xhi, *xlo, *Mhi, *Mlo, *Whi, *Wlo, *qvh, *qvl, *zhi, *zlo;
    cudaGetSymbolAddress((void**)&xhi, g_xhi);
    cudaGetSymbolAddress((void**)&xlo, g_xlo);
    cudaGetSymbolAddress((void**)&Mhi, g_Mhi);
    cudaGetSymbolAddress((void**)&Mlo, g_Mlo);
    cudaGetSymbolAddress((void**)&Whi, g_Whi);
    cudaGetSymbolAddress((void**)&Wlo, g_Wlo);
    cudaGetSymbolAddress((void**)&qvh, g_qvh);
    cudaGetSymbolAddress((void**)&qvl, g_qvl);
    cudaGetSymbolAddress((void**)&zhi, g_zhi);
    cudaGetSymbolAddress((void**)&zlo, g_zlo);

    cudaFuncSetAttribute(gemm_qk, cudaFuncAttributeMaxDynamicSharedMemorySize, QK_SMEM);
    cudaFuncSetAttribute(gemm_t<1>, cudaFuncAttributeMaxDynamicSharedMemorySize, GT_SMEM);
    cudaFuncSetAttribute(gemm_t<0>, cudaFuncAttributeMaxDynamicSharedMemorySize, GT_SMEM);
    cudaFuncSetAttribute(attn_mma, cudaFuncAttributeMaxDynamicSharedMemorySize, ATT_SMEM);

    // One-time streams + events (lazy; streams/events are not device memory).
    static cudaStream_t s1 = nullptr, s2 = nullptr, s3 = nullptr;
    static cudaEvent_t eFork = nullptr, eDone = nullptr;
    static cudaEvent_t eQK[BB], eV[BB], eA[BB];
    if (s1 == nullptr) {
        cudaStreamCreateWithFlags(&s1, cudaStreamNonBlocking);
        cudaStreamCreateWithFlags(&s2, cudaStreamNonBlocking);
        cudaStreamCreateWithFlags(&s3, cudaStreamNonBlocking);
        cudaEventCreateWithFlags(&eFork, cudaEventDisableTiming);
        cudaEventCreateWithFlags(&eDone, cudaEventDisableTiming);
        for (int b = 0; b < BB; b++) {
            cudaEventCreateWithFlags(&eQK[b], cudaEventDisableTiming);
            cudaEventCreateWithFlags(&eV[b], cudaEventDisableTiming);
            cudaEventCreateWithFlags(&eA[b], cudaEventDisableTiming);
        }
    }

    // Splits (legacy stream)
    {
        int n4 = NTOK * DD / 4;
        split_bf16<<<(n4 + 255) / 256, 256>>>(x, xhi, xlo, n4);
        n4 = 3 * DD * DD / 4;
        split_bf16<<<(n4 + 255) / 256, 256>>>(M, Mhi, Mlo, n4);
        n4 = DD * DD / 4;
        split_bf16<<<(n4 + 255) / 256, 256>>>(W, Wlo ? Whi : Whi, Wlo, n4);
    }

    cudaEventRecord(eFork, 0);
    cudaStreamWaitEvent(s1, eFork, 0);

    // Per-batch pipeline: QK(b) [legacy], V(b) [s1] -> attn(b) [s2] -> W(b) [s3]
    for (int b = 0; b < BB; b++) {
        const size_t roff = (size_t)b * TT;
        // QK(b): rows b*TT .. b*TT+2047
        {
            dim3 grid(2 * DD / 128, TT / 128);
            gemm_qk<<<grid, 128, QK_SMEM>>>(xhi + roff * DD, Mhi,
                                            qvh + roff * 3 * DD, 3 * DD, DD);
            cudaEventRecord(eQK[b], 0);
        }
        // V(b)
        {
            dim3 grid(DD / 64, TT / 128);
            gemm_t<1><<<grid, 128, GT_SMEM, s1>>>(
                xhi + roff * DD, xlo + roff * DD,
                Mhi + (size_t)2 * DD * DD, Mlo + (size_t)2 * DD * DD,
                nullptr, qvh + roff * 3 * DD + 2 * DD, qvl + roff * 3 * DD + 2 * DD,
                3 * DD, DD);
            cudaEventRecord(eV[b], s1);
        }
        // attn(b)
        {
            cudaStreamWaitEvent(s2, eQK[b], 0);
            cudaStreamWaitEvent(s2, eV[b], 0);
            dim3 grid(TT / 64, NHEAD, 1);
            attn_mma<<<grid, 128, ATT_SMEM, s2>>>(qvh, qvl, zhi, zlo, b);
            cudaEventRecord(eA[b], s2);
        }
        // W(b)
        {
            cudaStreamWaitEvent(s3, eA[b], 0);
            dim3 grid(DD / 64, TT / 128);
            gemm_t<0><<<grid, 128, GT_SMEM, s3>>>(
                zhi + roff * DD, zlo + roff * DD, Whi, Wlo,
                out + roff * DD, nullptr, nullptr, DD, DD);
        }
    }

    // Join everything back to the legacy stream.
    cudaEventRecord(eDone, s3);
    cudaStreamWaitEvent(0, eDone, 0);
}

// round 16
// speedup vs baseline: 1.0137x; 1.0137x over previous
#include <cuda_runtime.h>
#include <cuda_bf16.h>
#include <cstdint>

// Problem constants
#define BB 4
#define TT 2048
#define DD 1024
#define NHEAD 16
#define HD 64
#define NTOK (BB * TT)          // 8192

// ---------------------------------------------------------------------------
// Scratch (device globals; allocation is forbidden)
// ---------------------------------------------------------------------------
__device__ __nv_bfloat16 g_xhi[(size_t)NTOK * DD];
__device__ __nv_bfloat16 g_xlo[(size_t)NTOK * DD];
__device__ __nv_bfloat16 g_Mhi[(size_t)3 * DD * DD];
__device__ __nv_bfloat16 g_Mlo[(size_t)3 * DD * DD];
__device__ __nv_bfloat16 g_Whi[(size_t)DD * DD];
__device__ __nv_bfloat16 g_Wlo[(size_t)DD * DD];
__device__ __nv_bfloat16 g_qvh[(size_t)NTOK * 3 * DD];  // qkv hi (QK: hi only)
__device__ __nv_bfloat16 g_qvl[(size_t)NTOK * 3 * DD];  // qkv lo (V region only)
__device__ __nv_bfloat16 g_zhi[(size_t)NTOK * DD];
__device__ __nv_bfloat16 g_zlo[(size_t)NTOK * DD];

// ---------------------------------------------------------------------------
// Helpers
// ---------------------------------------------------------------------------
__device__ __forceinline__ uint32_t smem_u32(const void* p) {
    uint32_t a;
    asm("{ .reg .u64 t; cvta.to.shared.u64 t, %1; cvt.u32.u64 %0, t; }" : "=r"(a) : "l"(p));
    return a;
}
__device__ __forceinline__ uint32_t swz(uint32_t o) { return o ^ ((o >> 3) & 0x70); }

__device__ __forceinline__ void cp16(uint32_t s, const void* g) {
    asm volatile("cp.async.cg.shared.global [%0], [%1], 16;" :: "r"(s), "l"(g) : "memory");
}
__device__ __forceinline__ void cp_commit() {
    asm volatile("cp.async.commit_group;" ::: "memory");
}
__device__ __forceinline__ void ldsm4(uint32_t (&r)[4], uint32_t addr) {
    asm volatile("ldmatrix.sync.aligned.m8n8.x4.shared.b16 {%0,%1,%2,%3}, [%4];"
                 : "=r"(r[0]), "=r"(r[1]), "=r"(r[2]), "=r"(r[3]) : "r"(addr));
}
__device__ __forceinline__ void ldsm4t(uint32_t (&r)[4], uint32_t addr) {
    asm volatile("ldmatrix.sync.aligned.m8n8.x4.trans.shared.b16 {%0,%1,%2,%3}, [%4];"
                 : "=r"(r[0]), "=r"(r[1]), "=r"(r[2]), "=r"(r[3]) : "r"(addr));
}
__device__ __forceinline__ void mma16816(float (&d)[4], const uint32_t (&a)[4],
                                         uint32_t b0, uint32_t b1) {
    asm volatile("mma.sync.aligned.m16n8k16.row.col.f32.bf16.bf16.f32 "
                 "{%0,%1,%2,%3}, {%4,%5,%6,%7}, {%8,%9}, {%0,%1,%2,%3};"
                 : "+f"(d[0]), "+f"(d[1]), "+f"(d[2]), "+f"(d[3])
                 : "r"(a[0]), "r"(a[1]), "r"(a[2]), "r"(a[3]), "r"(b0), "r"(b1));
}
__device__ __forceinline__ uint32_t packbf(float lo, float hi) {
    uint32_t r;
    asm("cvt.rn.bf16x2.f32 %0, %1, %2;" : "=r"(r) : "f"(hi), "f"(lo));
    return r;
}
__device__ __forceinline__ float bfr(float f) {
    return __bfloat162float(__float2bfloat16(f));
}

// ---------------------------------------------------------------------------
// fp32 -> bf16 hi/lo split
// ---------------------------------------------------------------------------
__global__ __launch_bounds__(256) void split_bf16(const float* __restrict__ src,
                                                  __nv_bfloat16* __restrict__ hi,
                                                  __nv_bfloat16* __restrict__ lo,
                                                  int n4) {
    int i = blockIdx.x * blockDim.x + threadIdx.x;
    if (i >= n4) return;
    float4 v = ((const float4*)src)[i];
    float f[4] = {v.x, v.y, v.z, v.w};
    __nv_bfloat16 h[4], l[4];
#pragma unroll
    for (int j = 0; j < 4; j++) {
        h[j] = __float2bfloat16(f[j]);
        l[j] = __float2bfloat16(f[j] - __bfloat162float(h[j]));
    }
    ((uint2*)hi)[i] = *(uint2*)h;
    ((uint2*)lo)[i] = *(uint2*)l;
}

// ---------------------------------------------------------------------------
// QK projection GEMM (single-pass bf16): C = A[M,K]*B[N,K]^T, bf16 hi out.
//  CTA 128x128, 128 threads (4 warps, warp 64x64), NS=3 (96 KB) -> 2 CTAs/SM.
// ---------------------------------------------------------------------------
#define QK_ATILE 16384
#define QK_BTILE 16384
#define QK_STG   (QK_ATILE + QK_BTILE)   // 32768
#define QK_NS    3
#define QK_SMEM  (QK_NS * QK_STG)        // 98304

__global__ __launch_bounds__(128, 2)
void gemm_qk(const __nv_bfloat16* __restrict__ Ahi, const __nv_bfloat16* __restrict__ Bhi,
             __nv_bfloat16* __restrict__ Chi, int Ncols, int K) {
    extern __shared__ char smem[];
    const uint32_t sb = smem_u32(smem);
    const int tid = threadIdx.x;
    const int l   = tid & 31;
    const int wid = tid >> 5;
    const int row0 = blockIdx.y * 128;
    const int col0 = blockIdx.x * 128;
    const int wm0 = (wid & 1) * 64;
    const int wn0 = (wid >> 1) * 64;
    const int nchunk = K >> 6;

    const int lr_a = (l & 7) + ((l >> 3) & 1) * 8;
    const int ca   = ((l >> 4) & 1) * 8;
    const int lr_b = (l & 7) + ((l >> 4) & 1) * 8;
    const int cb   = ((l >> 3) & 1) * 8;

    float acc[4][8][4];
#pragma unroll
    for (int i = 0; i < 4; i++)
#pragma unroll
        for (int j = 0; j < 8; j++)
#pragma unroll
            for (int q = 0; q < 4; q++) acc[i][j][q] = 0.f;

    auto issue = [&](int buf, int k0) {
#pragma unroll
        for (int i = 0; i < 16; i++) {
            int u = tid + i * 128;           // 0..2047
            if (u < 1024) {
                int r = u >> 3, g = u & 7;
                cp16(sb + (uint32_t)buf * QK_STG + swz((uint32_t)(r * 128 + g * 16)),
                     Ahi + (size_t)(row0 + r) * K + k0 + g * 8);
            } else {
                int t = u - 1024;            // 0..1023
                int r = t >> 3, g = t & 7;   // r 0..127
                cp16(sb + (uint32_t)buf * QK_STG + QK_ATILE + swz((uint32_t)(r * 128 + g * 16)),
                     Bhi + (size_t)(col0 + r) * K + k0 + g * 8);
            }
        }
    };

#pragma unroll
    for (int s = 0; s < QK_NS - 1; s++) {
        issue(s, s << 6);
        cp_commit();
    }

    for (int c = 0; c < nchunk; c++) {
        asm volatile("cp.async.wait_group %0;" :: "n"(QK_NS - 2));
        __syncthreads();
        int cn = c + QK_NS - 1;
        if (cn < nchunk) issue(cn % QK_NS, cn << 6);
        cp_commit();

        const uint32_t stb = sb + (uint32_t)(c % QK_NS) * QK_STG;

#pragma unroll
        for (int ks = 0; ks < 4; ks++) {
            const int k0b = ks * 32;
            uint32_t ah[4][4];
#pragma unroll
            for (int i = 0; i < 4; i++)
                ldsm4(ah[i], stb + swz((uint32_t)((wm0 + i * 16 + lr_a) * 128 + k0b + ca * 2)));
            uint32_t bh[4][4];
#pragma unroll
            for (int jb = 0; jb < 4; jb++)
                ldsm4(bh[jb], stb + QK_ATILE + swz((uint32_t)((wn0 + jb * 16 + lr_b) * 128 + k0b + cb * 2)));
#pragma unroll
            for (int i = 0; i < 4; i++)
#pragma unroll
                for (int j = 0; j < 8; j++) {
                    int jb = j >> 1, p = (j & 1) * 2;
                    mma16816(acc[i][j], ah[i], bh[jb][p], bh[jb][p + 1]);
                }
        }
    }

    const int gq = l >> 2;
    const int tg = (l & 3) * 2;
#pragma unroll
    for (int i = 0; i < 4; i++) {
        int r = row0 + wm0 + i * 16 + gq;
#pragma unroll
        for (int j = 0; j < 8; j++) {
            int cc = col0 + wn0 + j * 8 + tg;
            size_t o0 = (size_t)r * Ncols + cc;
            size_t o1 = (size_t)(r + 8) * Ncols + cc;
            *reinterpret_cast<uint32_t*>(Chi + o0) = packbf(acc[i][j][0], acc[i][j][1]);
            *reinterpret_cast<uint32_t*>(Chi + o1) = packbf(acc[i][j][2], acc[i][j][3]);
        }
    }
}

// ---------------------------------------------------------------------------
// bf16x3 GEMM_NT (fp32-accurate):  C[M,N] = A[M,K] * B[N,K]^T
//  OMODE: 0 = fp32 C; 1 = bf16 hi/lo.
//  CTA 128x64, 128 threads (4 warps, warp 64x32), NS=2 (96 KB) -> 2 CTAs/SM.
// ---------------------------------------------------------------------------
#define GT_AT    16384                    // Ahi (128 rows x 128 B)
#define GT_BT    8192                     // Bhi (64 rows x 128 B)
#define GT_STG   (2 * GT_AT + 2 * GT_BT)  // 49152: {Ahi, Alo, Bhi, Blo}
#define GT_NS    2
#define GT_SMEM  (GT_NS * GT_STG)         // 98304

template <int OMODE>
__global__ __launch_bounds__(128, 2)
void gemm_t(const __nv_bfloat16* __restrict__ Ahi, const __nv_bfloat16* __restrict__ Alo,
            const __nv_bfloat16* __restrict__ Bhi, const __nv_bfloat16* __restrict__ Blo,
            float* __restrict__ C, __nv_bfloat16* __restrict__ Chi,
            __nv_bfloat16* __restrict__ Clo, int Ncols, int K) {
    extern __shared__ char smem[];
    const uint32_t sb = smem_u32(smem);
    const int tid = threadIdx.x;
    const int l   = tid & 31;
    const int wid = tid >> 5;
    const int row0 = blockIdx.y * 128;
    const int col0 = blockIdx.x * 64;
    const int wm0 = (wid & 1) * 64;
    const int wn0 = (wid >> 1) * 32;
    const int nchunk = K >> 6;

    const int lr_a = (l & 7) + ((l >> 3) & 1) * 8;
    const int ca   = ((l >> 4) & 1) * 8;
    const int lr_b = (l & 7) + ((l >> 4) & 1) * 8;
    const int cb   = ((l >> 3) & 1) * 8;

    float acc[4][4][4];
#pragma unroll
    for (int i = 0; i < 4; i++)
#pragma unroll
        for (int j = 0; j < 4; j++)
#pragma unroll
            for (int q = 0; q < 4; q++) acc[i][j][q] = 0.f;

    // stage layout: [Ahi 16K][Alo 16K][Bhi 8K][Blo 8K]
    auto issue = [&](int buf, int k0) {
        const uint32_t stg = sb + (uint32_t)buf * GT_STG;
#pragma unroll
        for (int i = 0; i < 24; i++) {
            int u = tid + i * 128;           // 0..3071
            if (u < 2048) {                  // A hi/lo: 2 x 1024
                int tl = u >> 10, t = u & 1023;
                int r = t >> 3, g = t & 7;
                const __nv_bfloat16* base = tl ? Alo : Ahi;
                cp16(stg + (uint32_t)tl * GT_AT + swz((uint32_t)(r * 128 + g * 16)),
                     base + (size_t)(row0 + r) * K + k0 + g * 8);
            } else {                         // B hi/lo: 2 x 512
                int t = u - 2048;
                int tl = t >> 9;  t &= 511;
                int r = t >> 3, g = t & 7;   // r 0..63
                const __nv_bfloat16* base = tl ? Blo : Bhi;
                cp16(stg + 2 * GT_AT + (uint32_t)tl * GT_BT + swz((uint32_t)(r * 128 + g * 16)),
                     base + (size_t)(col0 + r) * K + k0 + g * 8);
            }
        }
    };

    issue(0, 0);
    cp_commit();

    for (int c = 0; c < nchunk; c++) {
        asm volatile("cp.async.wait_group %0;" :: "n"(0));
        __syncthreads();
        if (c + 1 < nchunk) issue((c + 1) & 1, (c + 1) << 6);
        cp_commit();

        const uint32_t stb = sb + (uint32_t)(c & 1) * GT_STG;

#pragma unroll
        for (int ks = 0; ks < 4; ks++) {
            const int k0b = ks * 32;
            uint32_t ah[4][4], al[4][4];
#pragma unroll
            for (int i = 0; i < 4; i++) {
                uint32_t off = swz((uint32_t)((wm0 + i * 16 + lr_a) * 128 + k0b + ca * 2));
                ldsm4(ah[i], stb + off);
                ldsm4(al[i], stb + GT_AT + off);
            }
            uint32_t bh[2][4], bl[2][4];
#pragma unroll
            for (int h = 0; h < 2; h++) {
                uint32_t off = swz((uint32_t)((wn0 + h * 16 + lr_b) * 128 + k0b + cb * 2));
                ldsm4(bh[h], stb + 2 * GT_AT + off);
                ldsm4(bl[h], stb + 2 * GT_AT + GT_BT + off);
            }
            // pass 1: ah * bh
#pragma unroll
            for (int i = 0; i < 4; i++)
#pragma unroll
                for (int j = 0; j < 4; j++) {
                    int h = j >> 1, p = (j & 1) * 2;
                    mma16816(acc[i][j], ah[i], bh[h][p], bh[h][p + 1]);
                }
            // pass 2: ah * bl
#pragma unroll
            for (int i = 0; i < 4; i++)
#pragma unroll
                for (int j = 0; j < 4; j++) {
                    int h = j >> 1, p = (j & 1) * 2;
                    mma16816(acc[i][j], ah[i], bl[h][p], bl[h][p + 1]);
                }
            // pass 3: al * bh
#pragma unroll
            for (int i = 0; i < 4; i++)
#pragma unroll
                for (int j = 0; j < 4; j++) {
                    int h = j >> 1, p = (j & 1) * 2;
                    mma16816(acc[i][j], al[i], bh[h][p], bh[h][p + 1]);
                }
        }
    }

    const int gq = l >> 2;
    const int tg = (l & 3) * 2;
#pragma unroll
    for (int i = 0; i < 4; i++) {
        int r = row0 + wm0 + i * 16 + gq;
#pragma unroll
        for (int j = 0; j < 4; j++) {
            int cc = col0 + wn0 + j * 8 + tg;
            float v0 = acc[i][j][0], v1 = acc[i][j][1];
            float v2 = acc[i][j][2], v3 = acc[i][j][3];
            size_t o0 = (size_t)r * Ncols + cc;
            size_t o1 = (size_t)(r + 8) * Ncols + cc;
            if (OMODE == 0) {
                *(float2*)(C + o0) = make_float2(v0, v1);
                *(float2*)(C + o1) = make_float2(v2, v3);
            } else {
                float h0 = bfr(v0), h1 = bfr(v1), h2 = bfr(v2), h3 = bfr(v3);
                *reinterpret_cast<uint32_t*>(Chi + o0) = packbf(h0, h1);
                *reinterpret_cast<uint32_t*>(Clo + o0) = packbf(v0 - h0, v1 - h1);
                *reinterpret_cast<uint32_t*>(Chi + o1) = packbf(h2, h3);
                *reinterpret_cast<uint32_t*>(Clo + o1) = packbf(v2 - h2, v3 - h3);
            }
        }
    }
}

// ---------------------------------------------------------------------------
// Flash attention, mma.sync, no-max softmax (logits bounded -> shift 0 exact).
//  Br=64 (4 warps x m16), Bc=64, NS=2 stages (56 KB) -> 3 CTAs/SM.
//  b = bbase + blockIdx.z (half-batch pipelining).
// ---------------------------------------------------------------------------
#define ATT_TILE   8192
#define ATT_STAGE  (3 * ATT_TILE)                 // 24576: {Khi, Vhi, Vlo}
#define ATT_NS     2
#define ATT_SMEM   (ATT_TILE + ATT_NS * ATT_STAGE)   // 57344

__global__ __launch_bounds__(128, 3)
void attn_mma(const __nv_bfloat16* __restrict__ qvh, const __nv_bfloat16* __restrict__ qvl,
              __nv_bfloat16* __restrict__ zhi, __nv_bfloat16* __restrict__ zlo,
              int bbase) {
    extern __shared__ char smem[];
    const uint32_t sb = smem_u32(smem);
    const int tid = threadIdx.x, l = tid & 31, w = tid >> 5;
    const int qi = (TT / 64 - 1) - blockIdx.x;   // heavy CTAs first
    const int head = blockIdx.y, b = bbase + blockIdx.z;
    const int t0 = qi * 64;
    const int colK = head * HD;            // Qproj = keys
    const int colQ = DD + head * HD;       // Kproj = queries
    const int colV = 2 * DD + head * HD;   // V

    const int lr   = (l & 7) + ((l >> 3) & 1) * 8;
    const int ca16 = ((l >> 4) & 1) * 16;
    const int lr_b = (l & 7) + ((l >> 4) & 1) * 8;
    const int cb16 = ((l >> 3) & 1) * 16;

    auto issue_kv = [&](int kt, int buf) {
        const uint32_t stg = sb + ATT_TILE + (uint32_t)buf * ATT_STAGE;
#pragma unroll
        for (int i = 0; i < 12; i++) {
            int u = tid + i * 128;         // 0..1535
            int tl = u >> 9;               // 0:Khi 1:Vhi 2:Vlo
            int t = u & 511;
            int r = t >> 3, sg = t & 7;
            const __nv_bfloat16* base = (tl == 2) ? qvl : qvh;
            int col = tl ? colV : colK;
            cp16(stg + (uint32_t)tl * ATT_TILE + swz((uint32_t)(r * 128 + sg * 16)),
                 base + (size_t)(b * TT + kt * 64 + r) * (3 * DD) + col + sg * 8);
        }
    };

    // prologue: Q (hi only) + stage 0
#pragma unroll
    for (int i = 0; i < 4; i++) {
        int u = tid + i * 128;
        int r = u >> 3, sg = u & 7;
        cp16(sb + swz((uint32_t)(r * 128 + sg * 16)),
             qvh + (size_t)(b * TT + t0 + r) * (3 * DD) + colQ + sg * 8);
    }
    issue_kv(0, 0);
    cp_commit();

    float out[8][4];
#pragma unroll
    for (int j = 0; j < 8; j++)
#pragma unroll
        for (int q = 0; q < 4; q++) out[j][q] = 0.f;
    float ls0 = 0.f, ls1 = 0.f;   // lane-local; reduced in epilogue

    for (int kt = 0; kt <= qi; kt++) {
        asm volatile("cp.async.wait_group %0;" :: "n"(0));
        __syncthreads();
        if (kt + 1 <= qi) issue_kv(kt + 1, (kt + 1) & 1);
        cp_commit();

        const uint32_t stb = sb + ATT_TILE + (uint32_t)(kt & 1) * ATT_STAGE;

        // ---- S = Qhi . Khi^T (single pass) ----
        float sc[8][4];
#pragma unroll
        for (int j = 0; j < 8; j++)
#pragma unroll
            for (int q = 0; q < 4; q++) sc[j][q] = 0.f;
#pragma unroll
        for (int kk = 0; kk < 4; kk++) {
            uint32_t aqh[4];
            ldsm4(aqh, sb + swz((uint32_t)((w * 16 + lr) * 128 + kk * 32 + ca16)));
#pragma unroll
            for (int jb = 0; jb < 4; jb++) {
                uint32_t kbh[4];
                ldsm4(kbh, stb + swz((uint32_t)((jb * 16 + lr_b) * 128 + kk * 32 + cb16)));
                mma16816(sc[2 * jb],     aqh, kbh[0], kbh[1]);
                mma16816(sc[2 * jb + 1], aqh, kbh[2], kbh[3]);
            }
        }

        if (kt == qi) {   // diagonal tile: mask key i_local > t_local
            int tr0 = w * 16 + (l >> 2), tr1 = tr0 + 8;
            int ib = (l & 3) * 2;
#pragma unroll
            for (int j = 0; j < 8; j++) {
                int i0 = j * 8 + ib, i1 = i0 + 1;
                if (i0 > tr0) sc[j][0] = -1e30f;
                if (i1 > tr0) sc[j][1] = -1e30f;
                if (i0 > tr1) sc[j][2] = -1e30f;
                if (i1 > tr1) sc[j][3] = -1e30f;
            }
        }

        // ---- p = exp(s/8) (shift 0 exact; logits bounded) ----
#pragma unroll
        for (int j = 0; j < 8; j++) {
            sc[j][0] = __expf(sc[j][0] * 0.125f); ls0 += sc[j][0];
            sc[j][1] = __expf(sc[j][1] * 0.125f); ls0 += sc[j][1];
            sc[j][2] = __expf(sc[j][2] * 0.125f); ls1 += sc[j][2];
            sc[j][3] = __expf(sc[j][3] * 0.125f); ls1 += sc[j][3];
        }

        // ---- out += P.V  (pass-major: pah*vbh, pal*vbh, pah*vbl) ----
#pragma unroll
        for (int kk = 0; kk < 4; kk++) {
            uint32_t pah[4], pal[4];
#pragma unroll
            for (int h = 0; h < 2; h++) {
                int t2 = 2 * kk + h;
                float f0 = sc[t2][0], f1 = sc[t2][1], f2 = sc[t2][2], f3 = sc[t2][3];
                float h0 = bfr(f0), h1 = bfr(f1), h2 = bfr(f2), h3 = bfr(f3);
                pah[2 * h]     = packbf(h0, h1);
                pah[2 * h + 1] = packbf(h2, h3);
                pal[2 * h]     = packbf(f0 - h0, f1 - h1);
                pal[2 * h + 1] = packbf(f2 - h2, f3 - h3);
            }
            uint32_t vbh[4][4];
#pragma unroll
            for (int nb = 0; nb < 4; nb++)
                ldsm4t(vbh[nb], stb + ATT_TILE +
                       swz((uint32_t)((kk * 16 + lr) * 128 + nb * 32 + ca16)));
            // pass 1: pah * vbh
#pragma unroll
            for (int nb = 0; nb < 4; nb++) {
                mma16816(out[2 * nb],     pah, vbh[nb][0], vbh[nb][1]);
                mma16816(out[2 * nb + 1], pah, vbh[nb][2], vbh[nb][3]);
            }
            // pass 2: pal * vbh
#pragma unroll
            for (int nb = 0; nb < 4; nb++) {
                mma16816(out[2 * nb],     pal, vbh[nb][0], vbh[nb][1]);
                mma16816(out[2 * nb + 1], pal, vbh[nb][2], vbh[nb][3]);
            }
            // pass 3: pah * vbl
            uint32_t vbl[4][4];
#pragma unroll
            for (int nb = 0; nb < 4; nb++)
                ldsm4t(vbl[nb], stb + 2 * ATT_TILE +
                       swz((uint32_t)((kk * 16 + lr) * 128 + nb * 32 + ca16)));
#pragma unroll
            for (int nb = 0; nb < 4; nb++) {
                mma16816(out[2 * nb],     pah, vbl[nb][0], vbl[nb][1]);
                mma16816(out[2 * nb + 1], pah, vbl[nb][2], vbl[nb][3]);
            }
        }
    }

    // ---- epilogue: reduce lsum across quad, z = out / lsum, bf16 hi/lo ----
    ls0 += __shfl_xor_sync(0xffffffffu, ls0, 1);
    ls0 += __shfl_xor_sync(0xffffffffu, ls0, 2);
    ls1 += __shfl_xor_sync(0xffffffffu, ls1, 1);
    ls1 += __shfl_xor_sync(0xffffffffu, ls1, 2);
    float inv0 = 1.f / ls0, inv1 = 1.f / ls1;
    int tr0 = t0 + w * 16 + (l >> 2);
    size_t tok0 = (size_t)(b * TT + tr0) * DD;
    size_t tok1 = tok0 + (size_t)8 * DD;
    int colz = head * HD + (l & 3) * 2;
#pragma unroll
    for (int j = 0; j < 8; j++) {
        int cc = colz + j * 8;
        float v0 = out[j][0] * inv0, v1 = out[j][1] * inv0;
        float v2 = out[j][2] * inv1, v3 = out[j][3] * inv1;
        float h0 = bfr(v0), h1 = bfr(v1), h2 = bfr(v2), h3 = bfr(v3);
        *reinterpret_cast<uint32_t*>(zhi + tok0 + cc) = packbf(h0, h1);
        *reinterpret_cast<uint32_t*>(zlo + tok0 + cc) = packbf(v0 - h0, v1 - h1);
        *reinterpret_cast<uint32_t*>(zhi + tok1 + cc) = packbf(h2, h3);
        *reinterpret_cast<uint32_t*>(zlo + tok1 + cc) = packbf(v2 - h2, v3 - h3);
    }
}

// ---------------------------------------------------------------------------
extern "C" void kernel_launch(void* const* d_in, const int* in_sizes, int n_in,
                              void* d_out, int out_size) {
    const float* x = nullptr;
    const float* M = nullptr;
    const float* W = nullptr;
    for (int i = 0; i < n_in; i++) {
        if (in_sizes[i] == NTOK * DD)        x = (const float*)d_in[i];
        else if (in_sizes[i] == 3 * DD * DD) M = (const float*)d_in[i];
        else if (in_sizes[i] == DD * DD)     W = (const float*)d_in[i];
    }
    float* out = (float*)d_out;

    __nv_bfloat16 *xhi, *xlo, *Mhi, *Mlo, *Whi, *Wlo, *qvh, *qvl, *zhi, *zlo;
    cudaGetSymbolAddress((void**)&xhi, g_xhi);
    cudaGetSymbolAddress((void**)&xlo, g_xlo);
    cudaGetSymbolAddress((void**)&Mhi, g_Mhi);
    cudaGetSymbolAddress((void**)&Mlo, g_Mlo);
    cudaGetSymbolAddress((void**)&Whi, g_Whi);
    cudaGetSymbolAddress((void**)&Wlo, g_Wlo);
    cudaGetSymbolAddress((void**)&qvh, g_qvh);
    cudaGetSymbolAddress((void**)&qvl, g_qvl);
    cudaGetSymbolAddress((void**)&zhi, g_zhi);
    cudaGetSymbolAddress((void**)&zlo, g_zlo);

    cudaFuncSetAttribute(gemm_qk, cudaFuncAttributeMaxDynamicSharedMemorySize, QK_SMEM);
    cudaFuncSetAttribute(gemm_t<1>, cudaFuncAttributeMaxDynamicSharedMemorySize, GT_SMEM);
    cudaFuncSetAttribute(gemm_t<0>, cudaFuncAttributeMaxDynamicSharedMemorySize, GT_SMEM);
    cudaFuncSetAttribute(attn_mma, cudaFuncAttributeMaxDynamicSharedMemorySize, ATT_SMEM);

    // One-time streams + events (lazy; streams/events are not device memory).
    static cudaStream_t s1 = nullptr, s2 = nullptr, s3 = nullptr;
    static cudaEvent_t eFork = nullptr, eV = nullptr, eProj = nullptr;
    static cudaEvent_t eA0 = nullptr, eA1 = nullptr, eDone = nullptr;
    if (s1 == nullptr) {
        cudaStreamCreateWithFlags(&s1, cudaStreamNonBlocking);
        cudaStreamCreateWithFlags(&s2, cudaStreamNonBlocking);
        cudaStreamCreateWithFlags(&s3, cudaStreamNonBlocking);
        cudaEventCreateWithFlags(&eFork, cudaEventDisableTiming);
        cudaEventCreateWithFlags(&eV, cudaEventDisableTiming);
        cudaEventCreateWithFlags(&eProj, cudaEventDisableTiming);
        cudaEventCreateWithFlags(&eA0, cudaEventDisableTiming);
        cudaEventCreateWithFlags(&eA1, cudaEventDisableTiming);
        cudaEventCreateWithFlags(&eDone, cudaEventDisableTiming);
    }

    // Splits (legacy stream)
    {
        int n4 = NTOK * DD / 4;
        split_bf16<<<(n4 + 255) / 256, 256>>>(x, xhi, xlo, n4);
        n4 = 3 * DD * DD / 4;
        split_bf16<<<(n4 + 255) / 256, 256>>>(M, Mhi, Mlo, n4);
        n4 = DD * DD / 4;
        split_bf16<<<(n4 + 255) / 256, 256>>>(W, Whi, Wlo, n4);
    }

    // Fork: full V projection on s1 concurrently with full QK on legacy.
    cudaEventRecord(eFork, 0);
    cudaStreamWaitEvent(s1, eFork, 0);

    // 1a) Q,K projections (full, legacy stream)
    {
        dim3 grid(2 * DD / 128, NTOK / 128);
        gemm_qk<<<grid, 128, QK_SMEM>>>(xhi, Mhi, qvh, 3 * DD, DD);
    }
    // 1b) V projection (full, s1)
    {
        dim3 grid(DD / 64, NTOK / 128);
        gemm_t<1><<<grid, 128, GT_SMEM, s1>>>(
            xhi, xlo, Mhi + (size_t)2 * DD * DD, Mlo + (size_t)2 * DD * DD,
            nullptr, qvh + 2 * DD, qvl + 2 * DD, 3 * DD, DD);
        cudaEventRecord(eV, s1);
    }
    // Projections complete marker on legacy (QK done + V done).
    cudaStreamWaitEvent(0, eV, 0);
    cudaEventRecord(eProj, 0);

    // 2) attention in two halves on s2 (batches 0-1, then 2-3)
    cudaStreamWaitEvent(s2, eProj, 0);
    {
        dim3 grid(TT / 64, NHEAD, 2);
        attn_mma<<<grid, 128, ATT_SMEM, s2>>>(qvh, qvl, zhi, zlo, 0);
        cudaEventRecord(eA0, s2);
        attn_mma<<<grid, 128, ATT_SMEM, s2>>>(qvh, qvl, zhi, zlo, 2);
        cudaEventRecord(eA1, s2);
    }

    // 3) W projection in two halves on s3, each overlapping the other attn half
    {
        const size_t half = (size_t)2 * TT;   // 4096 rows
        dim3 grid(DD / 64, (unsigned)(half / 128));
        cudaStreamWaitEvent(s3, eA0, 0);
        gemm_t<0><<<grid, 128, GT_SMEM, s3>>>(
            zhi, zlo, Whi, Wlo, out, nullptr, nullptr, DD, DD);
        cudaStreamWaitEvent(s3, eA1, 0);
        gemm_t<0><<<grid, 128, GT_SMEM, s3>>>(
            zhi + half * DD, zlo + half * DD, Whi, Wlo,
            out + half * DD, nullptr, nullptr, DD, DD);
    }

    // Join everything back to the legacy stream.
    cudaEventRecord(eDone, s3);
    cudaStreamWaitEvent(0, eDone, 0);
}

// round 17
// speedup vs baseline: 1.0420x; 1.0279x over previous
#include <cuda_runtime.h>
#include <cuda_bf16.h>
#include <cstdint>

// Problem constants
#define BB 4
#define TT 2048
#define DD 1024
#define NHEAD 16
#define HD 64
#define NTOK (BB * TT)          // 8192

// ---------------------------------------------------------------------------
// Scratch (device globals; allocation is forbidden)
// ---------------------------------------------------------------------------
__device__ __nv_bfloat16 g_xhi[(size_t)NTOK * DD];
__device__ __nv_bfloat16 g_xlo[(size_t)NTOK * DD];
__device__ __nv_bfloat16 g_Mhi[(size_t)3 * DD * DD];
__device__ __nv_bfloat16 g_Mlo[(size_t)3 * DD * DD];
__device__ __nv_bfloat16 g_Whi[(size_t)DD * DD];
__device__ __nv_bfloat16 g_Wlo[(size_t)DD * DD];
__device__ __nv_bfloat16 g_qvh[(size_t)NTOK * 3 * DD];  // qkv hi (QK: hi only)
__device__ __nv_bfloat16 g_qvl[(size_t)NTOK * 3 * DD];  // qkv lo (V region only)
__device__ __nv_bfloat16 g_zhi[(size_t)NTOK * DD];
__device__ __nv_bfloat16 g_zlo[(size_t)NTOK * DD];

// ---------------------------------------------------------------------------
// Helpers
// ---------------------------------------------------------------------------
__device__ __forceinline__ uint32_t smem_u32(const void* p) {
    uint32_t a;
    asm("{ .reg .u64 t; cvta.to.shared.u64 t, %1; cvt.u32.u64 %0, t; }" : "=r"(a) : "l"(p));
    return a;
}
__device__ __forceinline__ uint32_t swz(uint32_t o) { return o ^ ((o >> 3) & 0x70); }

__device__ __forceinline__ void cp16(uint32_t s, const void* g) {
    asm volatile("cp.async.cg.shared.global [%0], [%1], 16;" :: "r"(s), "l"(g) : "memory");
}
__device__ __forceinline__ void cp_commit() {
    asm volatile("cp.async.commit_group;" ::: "memory");
}
__device__ __forceinline__ void ldsm4(uint32_t (&r)[4], uint32_t addr) {
    asm volatile("ldmatrix.sync.aligned.m8n8.x4.shared.b16 {%0,%1,%2,%3}, [%4];"
                 : "=r"(r[0]), "=r"(r[1]), "=r"(r[2]), "=r"(r[3]) : "r"(addr));
}
__device__ __forceinline__ void ldsm4t(uint32_t (&r)[4], uint32_t addr) {
    asm volatile("ldmatrix.sync.aligned.m8n8.x4.trans.shared.b16 {%0,%1,%2,%3}, [%4];"
                 : "=r"(r[0]), "=r"(r[1]), "=r"(r[2]), "=r"(r[3]) : "r"(addr));
}
__device__ __forceinline__ void mma16816(float (&d)[4], const uint32_t (&a)[4],
                                         uint32_t b0, uint32_t b1) {
    asm volatile("mma.sync.aligned.m16n8k16.row.col.f32.bf16.bf16.f32 "
                 "{%0,%1,%2,%3}, {%4,%5,%6,%7}, {%8,%9}, {%0,%1,%2,%3};"
                 : "+f"(d[0]), "+f"(d[1]), "+f"(d[2]), "+f"(d[3])
                 : "r"(a[0]), "r"(a[1]), "r"(a[2]), "r"(a[3]), "r"(b0), "r"(b1));
}
__device__ __forceinline__ uint32_t packbf(float lo, float hi) {
    uint32_t r;
    asm("cvt.rn.bf16x2.f32 %0, %1, %2;" : "=r"(r) : "f"(hi), "f"(lo));
    return r;
}
__device__ __forceinline__ float bfr(float f) {
    return __bfloat162float(__float2bfloat16(f));
}
// exp(s/8) as single ex2: arg = s * (0.125 * log2 e)
#define EXPC 0.18033688011112042f
__device__ __forceinline__ float ex2a(float x) {
    float r;
    asm("ex2.approx.f32 %0, %1;" : "=f"(r) : "f"(x));
    return r;
}

// ---------------------------------------------------------------------------
// fp32 -> bf16 hi/lo split
// ---------------------------------------------------------------------------
__global__ __launch_bounds__(256) void split_bf16(const float* __restrict__ src,
                                                  __nv_bfloat16* __restrict__ hi,
                                                  __nv_bfloat16* __restrict__ lo,
                                                  int n4) {
    int i = blockIdx.x * blockDim.x + threadIdx.x;
    if (i >= n4) return;
    float4 v = ((const float4*)src)[i];
    float f[4] = {v.x, v.y, v.z, v.w};
    __nv_bfloat16 h[4], l[4];
#pragma unroll
    for (int j = 0; j < 4; j++) {
        h[j] = __float2bfloat16(f[j]);
        l[j] = __float2bfloat16(f[j] - __bfloat162float(h[j]));
    }
    ((uint2*)hi)[i] = *(uint2*)h;
    ((uint2*)lo)[i] = *(uint2*)l;
}

// ---------------------------------------------------------------------------
// QK projection GEMM (single-pass bf16): C = A[M,K]*B[N,K]^T, bf16 hi out.
//  CTA 128x128, 128 threads (4 warps, warp 64x64), NS=3 (96 KB) -> 2 CTAs/SM.
// ---------------------------------------------------------------------------
#define QK_ATILE 16384
#define QK_BTILE 16384
#define QK_STG   (QK_ATILE + QK_BTILE)   // 32768
#define QK_NS    3
#define QK_SMEM  (QK_NS * QK_STG)        // 98304

__global__ __launch_bounds__(128, 2)
void gemm_qk(const __nv_bfloat16* __restrict__ Ahi, const __nv_bfloat16* __restrict__ Bhi,
             __nv_bfloat16* __restrict__ Chi, int Ncols, int K) {
    extern __shared__ char smem[];
    const uint32_t sb = smem_u32(smem);
    const int tid = threadIdx.x;
    const int l   = tid & 31;
    const int wid = tid >> 5;
    const int row0 = blockIdx.y * 128;
    const int col0 = blockIdx.x * 128;
    const int wm0 = (wid & 1) * 64;
    const int wn0 = (wid >> 1) * 64;
    const int nchunk = K >> 6;

    const int lr_a = (l & 7) + ((l >> 3) & 1) * 8;
    const int ca   = ((l >> 4) & 1) * 8;
    const int lr_b = (l & 7) + ((l >> 4) & 1) * 8;
    const int cb   = ((l >> 3) & 1) * 8;

    float acc[4][8][4];
#pragma unroll
    for (int i = 0; i < 4; i++)
#pragma unroll
        for (int j = 0; j < 8; j++)
#pragma unroll
            for (int q = 0; q < 4; q++) acc[i][j][q] = 0.f;

    auto issue = [&](int buf, int k0) {
#pragma unroll
        for (int i = 0; i < 16; i++) {
            int u = tid + i * 128;           // 0..2047
            if (u < 1024) {
                int r = u >> 3, g = u & 7;
                cp16(sb + (uint32_t)buf * QK_STG + swz((uint32_t)(r * 128 + g * 16)),
                     Ahi + (size_t)(row0 + r) * K + k0 + g * 8);
            } else {
                int t = u - 1024;            // 0..1023
                int r = t >> 3, g = t & 7;   // r 0..127
                cp16(sb + (uint32_t)buf * QK_STG + QK_ATILE + swz((uint32_t)(r * 128 + g * 16)),
                     Bhi + (size_t)(col0 + r) * K + k0 + g * 8);
            }
        }
    };

#pragma unroll
    for (int s = 0; s < QK_NS - 1; s++) {
        issue(s, s << 6);
        cp_commit();
    }

    for (int c = 0; c < nchunk; c++) {
        asm volatile("cp.async.wait_group %0;" :: "n"(QK_NS - 2));
        __syncthreads();
        int cn = c + QK_NS - 1;
        if (cn < nchunk) issue(cn % QK_NS, cn << 6);
        cp_commit();

        const uint32_t stb = sb + (uint32_t)(c % QK_NS) * QK_STG;

#pragma unroll
        for (int ks = 0; ks < 4; ks++) {
            const int k0b = ks * 32;
            uint32_t ah[4][4];
#pragma unroll
            for (int i = 0; i < 4; i++)
                ldsm4(ah[i], stb + swz((uint32_t)((wm0 + i * 16 + lr_a) * 128 + k0b + ca * 2)));
            uint32_t bh[4][4];
#pragma unroll
            for (int jb = 0; jb < 4; jb++)
                ldsm4(bh[jb], stb + QK_ATILE + swz((uint32_t)((wn0 + jb * 16 + lr_b) * 128 + k0b + cb * 2)));
#pragma unroll
            for (int i = 0; i < 4; i++)
#pragma unroll
                for (int j = 0; j < 8; j++) {
                    int jb = j >> 1, p = (j & 1) * 2;
                    mma16816(acc[i][j], ah[i], bh[jb][p], bh[jb][p + 1]);
                }
        }
    }

    const int gq = l >> 2;
    const int tg = (l & 3) * 2;
#pragma unroll
    for (int i = 0; i < 4; i++) {
        int r = row0 + wm0 + i * 16 + gq;
#pragma unroll
        for (int j = 0; j < 8; j++) {
            int cc = col0 + wn0 + j * 8 + tg;
            size_t o0 = (size_t)r * Ncols + cc;
            size_t o1 = (size_t)(r + 8) * Ncols + cc;
            *reinterpret_cast<uint32_t*>(Chi + o0) = packbf(acc[i][j][0], acc[i][j][1]);
            *reinterpret_cast<uint32_t*>(Chi + o1) = packbf(acc[i][j][2], acc[i][j][3]);
        }
    }
}

// ---------------------------------------------------------------------------
// bf16x3 GEMM_NT (fp32-accurate):  C[M,N] = A[M,K] * B[N,K]^T
//  OMODE: 0 = fp32 C; 1 = bf16 hi/lo.
//  CTA 128x64, 128 threads (4 warps, warp 64x32), NS=2 (96 KB) -> 2 CTAs/SM.
// ---------------------------------------------------------------------------
#define GT_AT    16384                    // Ahi (128 rows x 128 B)
#define GT_BT    8192                     // Bhi (64 rows x 128 B)
#define GT_STG   (2 * GT_AT + 2 * GT_BT)  // 49152: {Ahi, Alo, Bhi, Blo}
#define GT_NS    2
#define GT_SMEM  (GT_NS * GT_STG)         // 98304

template <int OMODE>
__global__ __launch_bounds__(128, 2)
void gemm_t(const __nv_bfloat16* __restrict__ Ahi, const __nv_bfloat16* __restrict__ Alo,
            const __nv_bfloat16* __restrict__ Bhi, const __nv_bfloat16* __restrict__ Blo,
            float* __restrict__ C, __nv_bfloat16* __restrict__ Chi,
            __nv_bfloat16* __restrict__ Clo, int Ncols, int K) {
    extern __shared__ char smem[];
    const uint32_t sb = smem_u32(smem);
    const int tid = threadIdx.x;
    const int l   = tid & 31;
    const int wid = tid >> 5;
    const int row0 = blockIdx.y * 128;
    const int col0 = blockIdx.x * 64;
    const int wm0 = (wid & 1) * 64;
    const int wn0 = (wid >> 1) * 32;
    const int nchunk = K >> 6;

    const int lr_a = (l & 7) + ((l >> 3) & 1) * 8;
    const int ca   = ((l >> 4) & 1) * 8;
    const int lr_b = (l & 7) + ((l >> 4) & 1) * 8;
    const int cb   = ((l >> 3) & 1) * 8;

    float acc[4][4][4];
#pragma unroll
    for (int i = 0; i < 4; i++)
#pragma unroll
        for (int j = 0; j < 4; j++)
#pragma unroll
            for (int q = 0; q < 4; q++) acc[i][j][q] = 0.f;

    // stage layout: [Ahi 16K][Alo 16K][Bhi 8K][Blo 8K]
    auto issue = [&](int buf, int k0) {
        const uint32_t stg = sb + (uint32_t)buf * GT_STG;
#pragma unroll
        for (int i = 0; i < 24; i++) {
            int u = tid + i * 128;           // 0..3071
            if (u < 2048) {                  // A hi/lo: 2 x 1024
                int tl = u >> 10, t = u & 1023;
                int r = t >> 3, g = t & 7;
                const __nv_bfloat16* base = tl ? Alo : Ahi;
                cp16(stg + (uint32_t)tl * GT_AT + swz((uint32_t)(r * 128 + g * 16)),
                     base + (size_t)(row0 + r) * K + k0 + g * 8);
            } else {                         // B hi/lo: 2 x 512
                int t = u - 2048;
                int tl = t >> 9;  t &= 511;
                int r = t >> 3, g = t & 7;   // r 0..63
                const __nv_bfloat16* base = tl ? Blo : Bhi;
                cp16(stg + 2 * GT_AT + (uint32_t)tl * GT_BT + swz((uint32_t)(r * 128 + g * 16)),
                     base + (size_t)(col0 + r) * K + k0 + g * 8);
            }
        }
    };

    issue(0, 0);
    cp_commit();

    for (int c = 0; c < nchunk; c++) {
        asm volatile("cp.async.wait_group %0;" :: "n"(0));
        __syncthreads();
        if (c + 1 < nchunk) issue((c + 1) & 1, (c + 1) << 6);
        cp_commit();

        const uint32_t stb = sb + (uint32_t)(c & 1) * GT_STG;

#pragma unroll
        for (int ks = 0; ks < 4; ks++) {
            const int k0b = ks * 32;
            uint32_t ah[4][4], al[4][4];
#pragma unroll
            for (int i = 0; i < 4; i++) {
                uint32_t off = swz((uint32_t)((wm0 + i * 16 + lr_a) * 128 + k0b + ca * 2));
                ldsm4(ah[i], stb + off);
                ldsm4(al[i], stb + GT_AT + off);
            }
            uint32_t bh[2][4], bl[2][4];
#pragma unroll
            for (int h = 0; h < 2; h++) {
                uint32_t off = swz((uint32_t)((wn0 + h * 16 + lr_b) * 128 + k0b + cb * 2));
                ldsm4(bh[h], stb + 2 * GT_AT + off);
                ldsm4(bl[h], stb + 2 * GT_AT + GT_BT + off);
            }
            // pass 1: ah * bh
#pragma unroll
            for (int i = 0; i < 4; i++)
#pragma unroll
                for (int j = 0; j < 4; j++) {
                    int h = j >> 1, p = (j & 1) * 2;
                    mma16816(acc[i][j], ah[i], bh[h][p], bh[h][p + 1]);
                }
            // pass 2: ah * bl
#pragma unroll
            for (int i = 0; i < 4; i++)
#pragma unroll
                for (int j = 0; j < 4; j++) {
                    int h = j >> 1, p = (j & 1) * 2;
                    mma16816(acc[i][j], ah[i], bl[h][p], bl[h][p + 1]);
                }
            // pass 3: al * bh
#pragma unroll
            for (int i = 0; i < 4; i++)
#pragma unroll
                for (int j = 0; j < 4; j++) {
                    int h = j >> 1, p = (j & 1) * 2;
                    mma16816(acc[i][j], al[i], bh[h][p], bh[h][p + 1]);
                }
        }
    }

    const int gq = l >> 2;
    const int tg = (l & 3) * 2;
#pragma unroll
    for (int i = 0; i < 4; i++) {
        int r = row0 + wm0 + i * 16 + gq;
#pragma unroll
        for (int j = 0; j < 4; j++) {
            int cc = col0 + wn0 + j * 8 + tg;
            float v0 = acc[i][j][0], v1 = acc[i][j][1];
            float v2 = acc[i][j][2], v3 = acc[i][j][3];
            size_t o0 = (size_t)r * Ncols + cc;
            size_t o1 = (size_t)(r + 8) * Ncols + cc;
            if (OMODE == 0) {
                *(float2*)(C + o0) = make_float2(v0, v1);
                *(float2*)(C + o1) = make_float2(v2, v3);
            } else {
                float h0 = bfr(v0), h1 = bfr(v1), h2 = bfr(v2), h3 = bfr(v3);
                *reinterpret_cast<uint32_t*>(Chi + o0) = packbf(h0, h1);
                *reinterpret_cast<uint32_t*>(Clo + o0) = packbf(v0 - h0, v1 - h1);
                *reinterpret_cast<uint32_t*>(Chi + o1) = packbf(h2, h3);
                *reinterpret_cast<uint32_t*>(Clo + o1) = packbf(v2 - h2, v3 - h3);
            }
        }
    }
}

// ---------------------------------------------------------------------------
// Flash attention, mma.sync, no-max softmax (logits bounded -> shift 0 exact).
//  Br=64 (4 warps x m16), Bc=64, NS=2 stages (56 KB) -> 3 CTAs/SM.
//  p = ex2(s * 0.125*log2e): one FMUL + one MUFU per element.
// ---------------------------------------------------------------------------
#define ATT_TILE   8192
#define ATT_STAGE  (3 * ATT_TILE)                 // 24576: {Khi, Vhi, Vlo}
#define ATT_NS     2
#define ATT_SMEM   (ATT_TILE + ATT_NS * ATT_STAGE)   // 57344

__global__ __launch_bounds__(128, 3)
void attn_mma(const __nv_bfloat16* __restrict__ qvh, const __nv_bfloat16* __restrict__ qvl,
              __nv_bfloat16* __restrict__ zhi, __nv_bfloat16* __restrict__ zlo) {
    extern __shared__ char smem[];
    const uint32_t sb = smem_u32(smem);
    const int tid = threadIdx.x, l = tid & 31, w = tid >> 5;
    const int qi = (TT / 64 - 1) - blockIdx.x;   // heavy CTAs first
    const int head = blockIdx.y, b = blockIdx.z;
    const int t0 = qi * 64;
    const int colK = head * HD;            // Qproj = keys
    const int colQ = DD + head * HD;       // Kproj = queries
    const int colV = 2 * DD + head * HD;   // V

    const int lr   = (l & 7) + ((l >> 3) & 1) * 8;
    const int ca16 = ((l >> 4) & 1) * 16;
    const int lr_b = (l & 7) + ((l >> 4) & 1) * 8;
    const int cb16 = ((l >> 3) & 1) * 16;

    auto issue_kv = [&](int kt, int buf) {
        const uint32_t stg = sb + ATT_TILE + (uint32_t)buf * ATT_STAGE;
#pragma unroll
        for (int i = 0; i < 12; i++) {
            int u = tid + i * 128;         // 0..1535
            int tl = u >> 9;               // 0:Khi 1:Vhi 2:Vlo
            int t = u & 511;
            int r = t >> 3, sg = t & 7;
            const __nv_bfloat16* base = (tl == 2) ? qvl : qvh;
            int col = tl ? colV : colK;
            cp16(stg + (uint32_t)tl * ATT_TILE + swz((uint32_t)(r * 128 + sg * 16)),
                 base + (size_t)(b * TT + kt * 64 + r) * (3 * DD) + col + sg * 8);
        }
    };

    // prologue: Q (hi only) + stage 0
#pragma unroll
    for (int i = 0; i < 4; i++) {
        int u = tid + i * 128;
        int r = u >> 3, sg = u & 7;
        cp16(sb + swz((uint32_t)(r * 128 + sg * 16)),
             qvh + (size_t)(b * TT + t0 + r) * (3 * DD) + colQ + sg * 8);
    }
    issue_kv(0, 0);
    cp_commit();

    float out[8][4];
#pragma unroll
    for (int j = 0; j < 8; j++)
#pragma unroll
        for (int q = 0; q < 4; q++) out[j][q] = 0.f;
    float ls0 = 0.f, ls1 = 0.f;   // lane-local; reduced in epilogue

    for (int kt = 0; kt <= qi; kt++) {
        asm volatile("cp.async.wait_group %0;" :: "n"(0));
        __syncthreads();
        if (kt + 1 <= qi) issue_kv(kt + 1, (kt + 1) & 1);
        cp_commit();

        const uint32_t stb = sb + ATT_TILE + (uint32_t)(kt & 1) * ATT_STAGE;

        // ---- S = Qhi . Khi^T (single pass) ----
        float sc[8][4];
#pragma unroll
        for (int j = 0; j < 8; j++)
#pragma unroll
            for (int q = 0; q < 4; q++) sc[j][q] = 0.f;
#pragma unroll
        for (int kk = 0; kk < 4; kk++) {
            uint32_t aqh[4];
            ldsm4(aqh, sb + swz((uint32_t)((w * 16 + lr) * 128 + kk * 32 + ca16)));
#pragma unroll
            for (int jb = 0; jb < 4; jb++) {
                uint32_t kbh[4];
                ldsm4(kbh, stb + swz((uint32_t)((jb * 16 + lr_b) * 128 + kk * 32 + cb16)));
                mma16816(sc[2 * jb],     aqh, kbh[0], kbh[1]);
                mma16816(sc[2 * jb + 1], aqh, kbh[2], kbh[3]);
            }
        }

        if (kt == qi) {   // diagonal tile: mask key i_local > t_local
            int tr0 = w * 16 + (l >> 2), tr1 = tr0 + 8;
            int ib = (l & 3) * 2;
#pragma unroll
            for (int j = 0; j < 8; j++) {
                int i0 = j * 8 + ib, i1 = i0 + 1;
                if (i0 > tr0) sc[j][0] = -1e30f;
                if (i1 > tr0) sc[j][1] = -1e30f;
                if (i0 > tr1) sc[j][2] = -1e30f;
                if (i1 > tr1) sc[j][3] = -1e30f;
            }
        }

        // ---- p = ex2(s * 0.125*log2e) (shift 0 exact; logits bounded) ----
#pragma unroll
        for (int j = 0; j < 8; j++) {
            sc[j][0] = ex2a(sc[j][0] * EXPC); ls0 += sc[j][0];
            sc[j][1] = ex2a(sc[j][1] * EXPC); ls0 += sc[j][1];
            sc[j][2] = ex2a(sc[j][2] * EXPC); ls1 += sc[j][2];
            sc[j][3] = ex2a(sc[j][3] * EXPC); ls1 += sc[j][3];
        }

        // ---- out += P.V  (pass-major: pah*vbh, pal*vbh, pah*vbl) ----
#pragma unroll
        for (int kk = 0; kk < 4; kk++) {
            uint32_t pah[4], pal[4];
#pragma unroll
            for (int h = 0; h < 2; h++) {
                int t2 = 2 * kk + h;
                float f0 = sc[t2][0], f1 = sc[t2][1], f2 = sc[t2][2], f3 = sc[t2][3];
                float h0 = bfr(f0), h1 = bfr(f1), h2 = bfr(f2), h3 = bfr(f3);
                pah[2 * h]     = packbf(h0, h1);
                pah[2 * h + 1] = packbf(h2, h3);
                pal[2 * h]     = packbf(f0 - h0, f1 - h1);
                pal[2 * h + 1] = packbf(f2 - h2, f3 - h3);
            }
            uint32_t vbh[4][4];
#pragma unroll
            for (int nb = 0; nb < 4; nb++)
                ldsm4t(vbh[nb], stb + ATT_TILE +
                       swz((uint32_t)((kk * 16 + lr) * 128 + nb * 32 + ca16)));
            // pass 1: pah * vbh
#pragma unroll
            for (int nb = 0; nb < 4; nb++) {
                mma16816(out[2 * nb],     pah, vbh[nb][0], vbh[nb][1]);
                mma16816(out[2 * nb + 1], pah, vbh[nb][2], vbh[nb][3]);
            }
            // pass 2: pal * vbh
#pragma unroll
            for (int nb = 0; nb < 4; nb++) {
                mma16816(out[2 * nb],     pal, vbh[nb][0], vbh[nb][1]);
                mma16816(out[2 * nb + 1], pal, vbh[nb][2], vbh[nb][3]);
            }
            // pass 3: pah * vbl
            uint32_t vbl[4][4];
#pragma unroll
            for (int nb = 0; nb < 4; nb++)
                ldsm4t(vbl[nb], stb + 2 * ATT_TILE +
                       swz((uint32_t)((kk * 16 + lr) * 128 + nb * 32 + ca16)));
#pragma unroll
            for (int nb = 0; nb < 4; nb++) {
                mma16816(out[2 * nb],     pah, vbl[nb][0], vbl[nb][1]);
                mma16816(out[2 * nb + 1], pah, vbl[nb][2], vbl[nb][3]);
            }
        }
    }

    // ---- epilogue: reduce lsum across quad, z = out / lsum, bf16 hi/lo ----
    ls0 += __shfl_xor_sync(0xffffffffu, ls0, 1);
    ls0 += __shfl_xor_sync(0xffffffffu, ls0, 2);
    ls1 += __shfl_xor_sync(0xffffffffu, ls1, 1);
    ls1 += __shfl_xor_sync(0xffffffffu, ls1, 2);
    float inv0 = 1.f / ls0, inv1 = 1.f / ls1;
    int tr0 = t0 + w * 16 + (l >> 2);
    size_t tok0 = (size_t)(b * TT + tr0) * DD;
    size_t tok1 = tok0 + (size_t)8 * DD;
    int colz = head * HD + (l & 3) * 2;
#pragma unroll
    for (int j = 0; j < 8; j++) {
        int cc = colz + j * 8;
        float v0 = out[j][0] * inv0, v1 = out[j][1] * inv0;
        float v2 = out[j][2] * inv1, v3 = out[j][3] * inv1;
        float h0 = bfr(v0), h1 = bfr(v1), h2 = bfr(v2), h3 = bfr(v3);
        *reinterpret_cast<uint32_t*>(zhi + tok0 + cc) = packbf(h0, h1);
        *reinterpret_cast<uint32_t*>(zlo + tok0 + cc) = packbf(v0 - h0, v1 - h1);
        *reinterpret_cast<uint32_t*>(zhi + tok1 + cc) = packbf(h2, h3);
        *reinterpret_cast<uint32_t*>(zlo + tok1 + cc) = packbf(v2 - h2, v3 - h3);
    }
}

// ---------------------------------------------------------------------------
extern "C" void kernel_launch(void* const* d_in, const int* in_sizes, int n_in,
                              void* d_out, int out_size) {
    const float* x = nullptr;
    const float* M = nullptr;
    const float* W = nullptr;
    for (int i = 0; i < n_in; i++) {
        if (in_sizes[i] == NTOK * DD)        x = (const float*)d_in[i];
        else if (in_sizes[i] == 3 * DD * DD) M = (const float*)d_in[i];
        else if (in_sizes[i] == DD * DD)     W = (const float*)d_in[i];
    }
    float* out = (float*)d_out;

    __nv_bfloat16 *xhi, *xlo, *Mhi, *Mlo, *Whi, *Wlo, *qvh, *qvl, *zhi, *zlo;
    cudaGetSymbolAddress((void**)&xhi, g_xhi);
    cudaGetSymbolAddress((void**)&xlo, g_xlo);
    cudaGetSymbolAddress((void**)&Mhi, g_Mhi);
    cudaGetSymbolAddress((void**)&Mlo, g_Mlo);
    cudaGetSymbolAddress((void**)&Whi, g_Whi);
    cudaGetSymbolAddress((void**)&Wlo, g_Wlo);
    cudaGetSymbolAddress((void**)&qvh, g_qvh);
    cudaGetSymbolAddress((void**)&qvl, g_qvl);
    cudaGetSymbolAddress((void**)&zhi, g_zhi);
    cudaGetSymbolAddress((void**)&zlo, g_zlo);

    cudaFuncSetAttribute(gemm_qk, cudaFuncAttributeMaxDynamicSharedMemorySize, QK_SMEM);
    cudaFuncSetAttribute(gemm_t<1>, cudaFuncAttributeMaxDynamicSharedMemorySize, GT_SMEM);
    cudaFuncSetAttribute(gemm_t<0>, cudaFuncAttributeMaxDynamicSharedMemorySize, GT_SMEM);
    cudaFuncSetAttribute(attn_mma, cudaFuncAttributeMaxDynamicSharedMemorySize, ATT_SMEM);

    // One-time side stream + fork/join events (created lazily; no device mem).
    static cudaStream_t s1 = nullptr;
    static cudaEvent_t eFork = nullptr, eJoin = nullptr;
    if (s1 == nullptr) {
        cudaStreamCreateWithFlags(&s1, cudaStreamNonBlocking);
        cudaEventCreateWithFlags(&eFork, cudaEventDisableTiming);
        cudaEventCreateWithFlags(&eJoin, cudaEventDisableTiming);
    }

    // Split inputs into bf16 hi/lo (legacy stream)
    {
        int n4 = NTOK * DD / 4;
        split_bf16<<<(n4 + 255) / 256, 256>>>(x, xhi, xlo, n4);
        n4 = 3 * DD * DD / 4;
        split_bf16<<<(n4 + 255) / 256, 256>>>(M, Mhi, Mlo, n4);
        n4 = DD * DD / 4;
        split_bf16<<<(n4 + 255) / 256, 256>>>(W, Whi, Wlo, n4);
    }

    // Fork: V projection runs on s1 concurrently with QK projection on legacy.
    cudaEventRecord(eFork, 0);
    cudaStreamWaitEvent(s1, eFork, 0);

    // 1a) Q,K projections: single-pass bf16, hi-only output (legacy stream)
    {
        dim3 grid(2 * DD / 128, NTOK / 128);
        gemm_qk<<<grid, 128, QK_SMEM>>>(xhi, Mhi, qvh, 3 * DD, DD);
    }
    // 1b) V projection: bf16x3, hi/lo output (stream s1)
    {
        dim3 grid(DD / 64, NTOK / 128);
        gemm_t<1><<<grid, 128, GT_SMEM, s1>>>(
            xhi, xlo, Mhi + (size_t)2 * DD * DD, Mlo + (size_t)2 * DD * DD,
            nullptr, qvh + 2 * DD, qvl + 2 * DD, 3 * DD, DD);
    }

    // Join: attention needs both projections.
    cudaEventRecord(eJoin, s1);
    cudaStreamWaitEvent(0, eJoin, 0);

    // 2) attention -> zhi/zlo
    {
        dim3 grid(TT / 64, NHEAD, BB);
        attn_mma<<<grid, 128, ATT_SMEM>>>(qvh, qvl, zhi, zlo);
    }
    // 3) out = z @ W^T (bf16x3, fp32 output)
    {
        dim3 grid(DD / 64, NTOK / 128);
        gemm_t<0><<<grid, 128, GT_SMEM>>>(
            zhi, zlo, Whi, Wlo, out, nullptr, nullptr, DD, DD);
    }
}